// round 8
// baseline (speedup 1.0000x reference)
#include <cuda_runtime.h>
#include <cstdint>

#define NPIX   9216
#define HW_    96
#define CIN_   256
#define EMB1_  256
#define EMB2_  128
#define NCLS_  80
#define NEG_   3
#define BATCH_ 8

// ---------------- device scratch (allocation-free) ----------------
__device__ float g_xf [(size_t)BATCH_ * NPIX * CIN_];   // x NHWC, tf32-rounded fp32
__device__ float g_hf [(size_t)BATCH_ * NPIX * EMB1_];  // conv1+BN out, tf32-rounded fp32
__device__ float g_emb[(size_t)BATCH_ * NPIX * EMB2_];  // conv2 out, pixel-major fp32
__device__ float g_wf1[EMB1_ * 9 * 256];                // W1 as [co][tap][ci], tf32-rounded
__device__ float g_wf2[EMB2_ * 9 * 256];                // W2 same
__device__ float g_reps[NCLS_ * EMB2_];
__device__ float g_repsneg[NCLS_ * NEG_ * EMB2_];

// ---------------- helpers ----------------
__device__ __forceinline__ float to_tf32(float x) {
    uint32_t u;
    asm("cvt.rna.tf32.f32 %0, %1;" : "=r"(u) : "f"(x));
    return __uint_as_float(u);
}
#define MMA_TF32(d, a, b0, b1) \
    asm volatile("mma.sync.aligned.m16n8k8.row.col.f32.tf32.tf32.f32 " \
        "{%0,%1,%2,%3}, {%4,%5,%6,%7}, {%8,%9}, {%0,%1,%2,%3};" \
        : "+f"((d)[0]), "+f"((d)[1]), "+f"((d)[2]), "+f"((d)[3]) \
        : "r"((a)[0]), "r"((a)[1]), "r"((a)[2]), "r"((a)[3]), "r"(b0), "r"(b1))

// ---------------------------------------------------------------------------
// pre-pass: x NCHW fp32 -> NHWC tf32-rounded fp32
// ---------------------------------------------------------------------------
__global__ __launch_bounds__(256)
void transpose_x_kernel(const float* __restrict__ x)
{
    __shared__ float s32[256 * 33];
    const int tid = threadIdx.x;
    const int b = blockIdx.y;
    const int p0 = blockIdx.x * 32;
    const int pxr = tid & 31, chb = tid >> 5;
#pragma unroll 4
    for (int pass = 0; pass < 32; ++pass) {
        int ch = pass * 8 + chb;
        s32[ch * 33 + pxr] = to_tf32(x[((size_t)(b * 256 + ch)) * NPIX + p0 + pxr]);
    }
    __syncthreads();
    for (int px = 0; px < 32; ++px) {
        g_xf[((size_t)(b * NPIX + p0 + px)) * 256 + tid] = s32[tid * 33 + px];
    }
}

// ---------------------------------------------------------------------------
// pre-pass: W [co][256][3][3] fp32 -> [co][tap][ci] tf32-rounded fp32
// ---------------------------------------------------------------------------
__global__ __launch_bounds__(256)
void wprep_kernel(const float* __restrict__ w, float* __restrict__ dst, int total)
{
    int i = blockIdx.x * 256 + threadIdx.x;
    if (i >= total) return;
    int co = i / 2304, r = i - co * 2304;
    int t = r >> 8;
    int ci = r & 255;
    dst[i] = to_tf32(w[((size_t)(co * 256 + ci)) * 9 + t]);
}

// ---------------------------------------------------------------------------
// tf32 mma conv (unchanged from passing R7)
// ---------------------------------------------------------------------------
template<int STAGE>
__global__ __launch_bounds__(256)
void conv_tf32(const float* __restrict__ bias,
               const float* __restrict__ gamma,
               const float* __restrict__ beta,
               const float* __restrict__ mean,
               const float* __restrict__ var)
{
    extern __shared__ float smf[];
    float* Xh = smf;               // [4 rows][98 xpos][36 stride]
    float* Ws = smf + 14112;       // [128 co][36 stride]

    const int tid = threadIdx.x, wid = tid >> 5, lane = tid & 31;
    const int y0 = blockIdx.x * 2;
    const int b  = blockIdx.y;
    const int co0 = blockIdx.z * 128;
    const int wq = wid & 3, wh = wid >> 2;
    const int gid = lane >> 2, tig = lane & 3;

    const float* __restrict__ src  = (STAGE == 1) ? g_xf : g_hf;
    const float* __restrict__ wsrc = (STAGE == 1) ? g_wf1 : g_wf2;

    float acc[2][12][4];
#pragma unroll
    for (int m = 0; m < 2; ++m)
#pragma unroll
        for (int n = 0; n < 12; ++n)
#pragma unroll
            for (int q = 0; q < 4; ++q) acc[m][n][q] = 0.f;

    const uint32_t* Wsu = reinterpret_cast<const uint32_t*>(Ws);
    const uint32_t* Xhu = reinterpret_cast<const uint32_t*>(Xh);
    int aidx[2], xidx[12];
#pragma unroll
    for (int mi = 0; mi < 2; ++mi)
        aidx[mi] = (wq * 32 + mi * 16 + gid) * 36 + tig;
#pragma unroll
    for (int p = 0; p < 12; ++p)
        xidx[p] = (wh * 98 + p * 8 + gid) * 36 + tig;

    for (int c = 0; c < 8; ++c) {
        __syncthreads();
        for (int i = tid; i < 3136; i += 256) {
            int pos = i >> 3, g = i & 7;
            int yrow = pos / 98, xpos = pos - yrow * 98;
            int y = y0 + yrow - 1, xc = xpos - 1;
            uint4 v = make_uint4(0u, 0u, 0u, 0u);
            if ((unsigned)y < 96u && (unsigned)xc < 96u)
                v = *reinterpret_cast<const uint4*>(
                    src + ((size_t)(b * NPIX + y * 96 + xc)) * 256 + c * 32 + g * 4);
            *reinterpret_cast<uint4*>(Xh + pos * 36 + g * 4) = v;
        }
        for (int tap = 0; tap < 9; ++tap) {
            const int kr = tap / 3, kc = tap - kr * 3;
            __syncthreads();
            for (int i = tid; i < 1024; i += 256) {
                int co = i >> 3, g = i & 7;
                uint4 v = *reinterpret_cast<const uint4*>(
                    wsrc + ((size_t)((co0 + co) * 9 + tap)) * 256 + c * 32 + g * 4);
                *reinterpret_cast<uint4*>(Ws + co * 36 + g * 4) = v;
            }
            __syncthreads();
            const int toff = (kr * 98 + kc) * 36;
#pragma unroll
            for (int ks = 0; ks < 4; ++ks) {
                const int k0 = ks * 8;
                uint32_t a[2][4];
#pragma unroll
                for (int mi = 0; mi < 2; ++mi) {
                    a[mi][0] = Wsu[aidx[mi] + k0];
                    a[mi][1] = Wsu[aidx[mi] + k0 + 8 * 36];
                    a[mi][2] = Wsu[aidx[mi] + k0 + 4];
                    a[mi][3] = Wsu[aidx[mi] + k0 + 8 * 36 + 4];
                }
#pragma unroll
                for (int p = 0; p < 12; ++p) {
                    uint32_t b0 = Xhu[xidx[p] + toff + k0];
                    uint32_t b1 = Xhu[xidx[p] + toff + k0 + 4];
                    MMA_TF32(acc[0][p], a[0], b0, b1);
                    MMA_TF32(acc[1][p], a[1], b0, b1);
                }
            }
        }
    }

    const size_t pixb = (size_t)b * NPIX + (size_t)(y0 + wh) * 96;
#pragma unroll
    for (int mi = 0; mi < 2; ++mi) {
        const int clo = co0 + wq * 32 + mi * 16 + gid;
        const int chi = clo + 8;
        float blo = bias[clo], bhi = bias[chi];
        float slo = 1.f, shi = 1.f, mlo = 0.f, mhi = 0.f, elo = 0.f, ehi = 0.f;
        if (STAGE == 1) {
            slo = gamma[clo] * rsqrtf(var[clo] + 1e-5f);
            shi = gamma[chi] * rsqrtf(var[chi] + 1e-5f);
            mlo = mean[clo]; mhi = mean[chi];
            elo = beta[clo]; ehi = beta[chi];
        }
#pragma unroll
        for (int n = 0; n < 12; ++n) {
            const int px0 = n * 8 + tig * 2;
#pragma unroll
            for (int j = 0; j < 2; ++j) {
                float vlo = acc[mi][n][j]     + blo;
                float vhi = acc[mi][n][j + 2] + bhi;
                const size_t pix = pixb + px0 + j;
                if (STAGE == 1) {
                    vlo = (vlo - mlo) * slo + elo;
                    vhi = (vhi - mhi) * shi + ehi;
                    g_hf[pix * 256 + clo] = to_tf32(vlo);
                    g_hf[pix * 256 + chi] = to_tf32(vhi);
                } else {
                    g_emb[pix * 128 + clo] = vlo;
                    g_emb[pix * 128 + chi] = vhi;
                }
            }
        }
    }
}

// ---------------------------------------------------------------------------
// L2-normalize emb (pixel-major), warp per pixel.
// ---------------------------------------------------------------------------
__global__ __launch_bounds__(256)
void normalize_emb_pm()
{
    const int gw = (blockIdx.x * 256 + threadIdx.x) >> 5;
    const int lane = threadIdx.x & 31;
    float4* e4 = reinterpret_cast<float4*>(g_emb + (size_t)gw * 128);
    float4 v = e4[lane];
    float ss = v.x * v.x + v.y * v.y + v.z * v.z + v.w * v.w;
#pragma unroll
    for (int o = 16; o > 0; o >>= 1) ss += __shfl_xor_sync(0xffffffffu, ss, o);
    float sc = 1.f / fmaxf(sqrtf(ss), 1e-12f);
    v.x *= sc; v.y *= sc; v.z *= sc; v.w *= sc;
    e4[lane] = v;
}

// ---------------------------------------------------------------------------
// reps prep v4: smem-staged transposed W (coalesced + conflict-free).
// ---------------------------------------------------------------------------
__device__ __forceinline__ float block_sumsq_128(float v, float* red4)
{
    float s = v * v;
#pragma unroll
    for (int o = 16; o > 0; o >>= 1) s += __shfl_xor_sync(0xffffffffu, s, o);
    const int wid = threadIdx.x >> 5, lane = threadIdx.x & 31;
    if (lane == 0) red4[wid] = s;
    __syncthreads();
    float tot = red4[0] + red4[1] + red4[2] + red4[3];
    __syncthreads();
    return tot;
}

__global__ __launch_bounds__(128)
void prep_reps_v4(const float* __restrict__ rep_w,
                  const float* __restrict__ rep_b,
                  const float* __restrict__ neg_w,
                  const float* __restrict__ neg_b)
{
    extern __shared__ float Wsm[];    // [128 k][129] transposed layer
    __shared__ float r_s[128];
    __shared__ float h_a[128];
    __shared__ float h_b[128];
    __shared__ float red4[4];

    const int j = threadIdx.x, c = blockIdx.x;

    float v = rep_w[c * 128 + j] + rep_b[c * 128 + j];
    float tot = block_sumsq_128(v, red4);
    float scale = 1.f / fmaxf(sqrtf(tot), 1e-12f);
    r_s[j] = v * scale;
    g_reps[c * 128 + j] = v * scale;
    __syncthreads();

    for (int n = 0; n < NEG_; ++n) {
        float accf = 0.f;
        const float* srcv = r_s;
#pragma unroll
        for (int i = 0; i < 3; ++i) {
            const float* W = neg_w + (size_t)((n * 3 + i) * 128) * 128;
            __syncthreads();
            // stage transposed: Wsm[k*129 + row] = W[row*128 + k]
            // thread j: ii = j + 128*t -> row=t, k=j. LDG coalesced, STS conflict-free.
            for (int ii = j; ii < 16384; ii += 128) {
                int row = ii >> 7, k = ii & 127;
                Wsm[k * 129 + row] = W[ii];
            }
            __syncthreads();
            float acc = neg_b[(n * 3 + i) * 128 + j];
#pragma unroll 8
            for (int k = 0; k < 128; ++k)
                acc = fmaf(srcv[k], Wsm[k * 129 + j], acc);
            if (i < 2) {
                acc = fmaxf(acc, 0.f);
                float* dst = (i == 0) ? h_a : h_b;
                dst[j] = acc;
                __syncthreads();
                srcv = dst;
            } else {
                accf = acc;
            }
        }
        float t2 = block_sumsq_128(accf, red4);
        float sc2 = 1.f / fmaxf(sqrtf(t2), 1e-12f);
        g_repsneg[((size_t)c * NEG_ + n) * 128 + j] = accf * sc2;
        __syncthreads();
    }
}

// ---------------------------------------------------------------------------
// dot via tf32 mma: block = 64 px x 320 reps (rep r = class*4 + kind,
// kind 0 = pos, 1..3 = neg). 10 warps = 5 rep-groups x 2 px-groups.
// Accumulators round-trip through smem dots[64px][321] so the epilogue is
// layout-independent. Same fragment maps as the (validated) conv kernel.
// ---------------------------------------------------------------------------
__global__ __launch_bounds__(320)
void dot_mma(float* __restrict__ out)
{
    extern __shared__ float sd[];
    float* reps_s = sd;            // [320][132] = 42240 floats
    float* emb_s  = sd + 42240;    // [64][132]  = 8448 floats
    float* dots_s = sd;            // overlay [64][321] = 20544 floats

    const int tid = threadIdx.x, wid = tid >> 5, lane = tid & 31;
    const int g = lane >> 2, tig = lane & 3;
    const int gpx0 = blockIdx.x * 64;     // global pixel over B*NPIX

    for (int i = tid; i < 40960; i += 320) {
        int r = i >> 7, k = i & 127;
        int cls = r >> 2, kind = r & 3;
        float v = (kind == 0) ? g_reps[cls * 128 + k]
                              : g_repsneg[(cls * 3 + (kind - 1)) * 128 + k];
        reps_s[r * 132 + k] = v;
    }
    for (int i = tid; i < 8192; i += 320) {
        int px = i >> 7, k = i & 127;
        emb_s[px * 132 + k] = g_emb[(size_t)(gpx0 + px) * 128 + k];
    }
    __syncthreads();

    const int wr = wid % 5;    // rep group (64 reps)
    const int wp = wid / 5;    // px group (32 px)
    float acc[4][4][4];
#pragma unroll
    for (int mi = 0; mi < 4; ++mi)
#pragma unroll
        for (int ni = 0; ni < 4; ++ni)
#pragma unroll
            for (int q = 0; q < 4; ++q) acc[mi][ni][q] = 0.f;

    const uint32_t* ru = reinterpret_cast<const uint32_t*>(reps_s) + (wr * 64) * 132;
    const uint32_t* eu = reinterpret_cast<const uint32_t*>(emb_s)  + (wp * 32) * 132;

    for (int ks = 0; ks < 16; ++ks) {
        const int k0 = ks * 8;
        uint32_t a[4][4];
#pragma unroll
        for (int mi = 0; mi < 4; ++mi) {
            const uint32_t* ab = ru + (mi * 16 + g) * 132 + k0;
            a[mi][0] = ab[tig];
            a[mi][1] = ab[8 * 132 + tig];
            a[mi][2] = ab[tig + 4];
            a[mi][3] = ab[8 * 132 + tig + 4];
        }
#pragma unroll
        for (int ni = 0; ni < 4; ++ni) {
            const uint32_t* bb = eu + (ni * 8 + g) * 132 + k0;
            uint32_t b0 = bb[tig], b1 = bb[tig + 4];
            MMA_TF32(acc[0][ni], a[0], b0, b1);
            MMA_TF32(acc[1][ni], a[1], b0, b1);
            MMA_TF32(acc[2][ni], a[2], b0, b1);
            MMA_TF32(acc[3][ni], a[3], b0, b1);
        }
    }
    __syncthreads();   // all mma done before overlay writes

#pragma unroll
    for (int mi = 0; mi < 4; ++mi)
#pragma unroll
        for (int ni = 0; ni < 4; ++ni) {
            int rep = wr * 64 + mi * 16 + g;
            int px  = wp * 32 + ni * 8 + tig * 2;
            dots_s[px * 321 + rep]           = acc[mi][ni][0];
            dots_s[(px + 1) * 321 + rep]     = acc[mi][ni][1];
            dots_s[px * 321 + rep + 8]       = acc[mi][ni][2];
            dots_s[(px + 1) * 321 + rep + 8] = acc[mi][ni][3];
        }
    __syncthreads();

    // epilogue: 320 threads = 20 class-slots x 16 px-quads; 4 classes each
    const int cc = tid >> 4;     // 0..19
    const int pg = tid & 15;
    const int b = gpx0 / NPIX;
    const int pimg = (gpx0 % NPIX) + pg * 4;
    const size_t S = (size_t)BATCH_ * NCLS_ * NPIX;
    float* out_cls  = out;
    float* out_csn  = out + S;
    float* out_dist = out + 2 * S;
    float* out_dneg = out + 3 * S;
    float* out_pori = out + 6 * S;

#pragma unroll
    for (int it = 0; it < 4; ++it) {
        const int c = it * 20 + cc;
        const size_t base   = ((size_t)b * NCLS_ + c) * NPIX + pimg;
        const size_t dnbase = ((size_t)(b * NCLS_ + c) * 3) * NPIX + pimg;
#pragma unroll
        for (int jx = 0; jx < 4; ++jx) {
            const float* q = dots_s + (size_t)(pg * 4 + jx) * 321 + c * 4;
            float dist = sqrtf(fmaxf(2.f - 2.f * q[0], 0.f));
            float dn0  = sqrtf(fmaxf(2.f - 2.f * q[1], 0.f));
            float dn1  = sqrtf(fmaxf(2.f - 2.f * q[2], 0.f));
            float dn2  = sqrtf(fmaxf(2.f - 2.f * q[3], 0.f));

            float pn0 = expf(-dn0 * dn0 * 2.f);
            float pn1 = expf(-dn1 * dn1 * 2.f);
            float pn2 = expf(-dn2 * dn2 * 2.f);
            float csn = fmaxf(pn0, fmaxf(pn1, pn2));

            float minn = fminf(dn0, fminf(dn1, dn2));
            float shifted = dist + 0.3f * fmaxf(2.f - minn, 0.f);
            float pr = expf(-shifted * shifted * 2.f);
            float cs = fminf(fmaxf(pr, 0.f), 1.f);
            float cls = logf(fmaxf(cs, 1e-5f) / fmaxf(1.f - cs, 1e-5f));
            float pori = expf(-dist * dist * 2.f);

            out_cls [base + jx] = cls;
            out_csn [base + jx] = csn;
            out_dist[base + jx] = dist;
            out_pori[base + jx] = pori;
            out_dneg[dnbase + jx]            = dn0;
            out_dneg[dnbase + NPIX + jx]     = dn1;
            out_dneg[dnbase + 2 * NPIX + jx] = dn2;
        }
    }
}

// ---------------------------------------------------------------------------
extern "C" void kernel_launch(void* const* d_in, const int* in_sizes, int n_in,
                              void* d_out, int out_size)
{
    const float* x      = (const float*)d_in[0];
    const float* w1     = (const float*)d_in[1];
    const float* b1     = (const float*)d_in[2];
    const float* gamma  = (const float*)d_in[3];
    const float* beta   = (const float*)d_in[4];
    const float* mean   = (const float*)d_in[5];
    const float* var    = (const float*)d_in[6];
    const float* w2     = (const float*)d_in[7];
    const float* b2     = (const float*)d_in[8];
    const float* rep_w  = (const float*)d_in[9];
    const float* rep_b  = (const float*)d_in[10];
    const float* neg_w  = (const float*)d_in[11];
    const float* neg_b  = (const float*)d_in[12];
    float* out = (float*)d_out;

    (void)in_sizes; (void)n_in; (void)out_size;

    const int CONV_SMEM = (14112 + 4608) * 4;       // 74880 B
    const int DOT_SMEM  = (42240 + 8448) * 4;       // 202752 B
    const int PREP_SMEM = 128 * 129 * 4;            // 66048 B
    cudaFuncSetAttribute(conv_tf32<1>, cudaFuncAttributeMaxDynamicSharedMemorySize, CONV_SMEM);
    cudaFuncSetAttribute(conv_tf32<2>, cudaFuncAttributeMaxDynamicSharedMemorySize, CONV_SMEM);
    cudaFuncSetAttribute(dot_mma,      cudaFuncAttributeMaxDynamicSharedMemorySize, DOT_SMEM);
    cudaFuncSetAttribute(prep_reps_v4, cudaFuncAttributeMaxDynamicSharedMemorySize, PREP_SMEM);

    float *wf1p, *wf2p;
    cudaGetSymbolAddress((void**)&wf1p, g_wf1);
    cudaGetSymbolAddress((void**)&wf2p, g_wf2);

    // pre-passes
    transpose_x_kernel<<<dim3(NPIX / 32, BATCH_), 256>>>(x);
    wprep_kernel<<<(EMB1_ * 2304 + 255) / 256, 256>>>(w1, wf1p, EMB1_ * 2304);
    wprep_kernel<<<(EMB2_ * 2304 + 255) / 256, 256>>>(w2, wf2p, EMB2_ * 2304);
    prep_reps_v4<<<NCLS_, 128, PREP_SMEM>>>(rep_w, rep_b, neg_w, neg_b);

    // conv1 + BN (tf32 mma)
    conv_tf32<1><<<dim3(48, BATCH_, 2), 256, CONV_SMEM>>>(b1, gamma, beta, mean, var);
    // conv2 (tf32 mma)
    conv_tf32<2><<<dim3(48, BATCH_, 1), 256, CONV_SMEM>>>(b2, nullptr, nullptr, nullptr, nullptr);

    // normalize emb (pixel-major)
    normalize_emb_pm<<<BATCH_ * NPIX / 8, 256>>>();

    // dot via tf32 mma + fused epilogue
    dot_mma<<<(size_t)BATCH_ * NPIX / 64, 320, DOT_SMEM>>>(out);
}